// round 4
// baseline (speedup 1.0000x reference)
#include <cuda_runtime.h>

// LRN, all-ones cross-channel 5x5 filter, fused single-read kernel.
//   s[b,h,w] = sum_c x^2 ; y = 5x5 box(s) ; out = x * (2 + 1e-4*y)^(-0.75)
//
// One block per (batch, 16x16 tile). 512 threads, 2 blocks/SM.
// Phase 1: 480 threads = 4 channel-quarters x 120 halo-quads; float4 loads;
//          interior x parked in SMEM (96KB); partial sums reduced in SMEM.
// Phase 2: 5x5 box + fast pow.
// Phase 3: scale from SMEM, float4 stores (no gmem re-read).

#define Bn 16
#define Cn 96
#define Hn 224
#define Wn 224
#define HWn (Hn * Wn)          // 50176
#define TH 16
#define TW 16
#define NPIX (TH * TW)         // 256
#define SROWS (TH + 4)         // 20 halo rows
#define SQ 6                   // quads per halo row ([w0-4, w0+20) = 24 floats)
#define SCOLS (SQ * 4)         // 24
#define NQ (SROWS * SQ)        // 120 halo quad positions
#define NTHREADS 512
#define CQ (Cn / 4)            // 24 channels per quarter
// smem (floats): x_s 24576 | part 4*120*4=1920 | s_s 480 | f_s 256
#define X_FLOATS (Cn * NPIX)
#define PART_OFF X_FLOATS
#define S_OFF (PART_OFF + 4 * NQ * 4)
#define F_OFF (S_OFF + SROWS * SCOLS)
#define SMEM_FLOATS (F_OFF + NPIX)
#define SMEM_BYTES (SMEM_FLOATS * 4)   // 106,528 B -> 2 blocks/SM

__global__ __launch_bounds__(NTHREADS, 2)
void lrn_fused_kernel(const float* __restrict__ x, float* __restrict__ out) {
    extern __shared__ float smem[];
    float4* x4_s  = (float4*)smem;                 // [96][64] interior quads
    float4* part  = (float4*)(smem + PART_OFF);    // [4][120] partial sums
    float*  s_s   = smem + S_OFF;                  // [20][24] summed squares
    float*  f_s   = smem + F_OFF;                  // [256] scale factors

    const int tid = threadIdx.x;
    const int b   = blockIdx.z;
    const int h0  = blockIdx.y * TH;
    const int w0  = blockIdx.x * TW;
    const int img = b * Cn * HWn;                  // <= 72.2M, int32 ok

    // ---------------- Phase 1: stream channels once (float4) -----------------
    {
        const int quarter = tid / NQ;              // 0..3 (>=4 -> idle)
        const int p  = tid - quarter * NQ;
        const bool active = tid < 4 * NQ;
        const int sr = p / SQ;
        const int sq = p - sr * SQ;
        const int gh = h0 - 2 + sr;
        const int gw = w0 - 4 + sq * 4;            // 16B-aligned; fully in or out
        const bool valid = active &&
            ((unsigned)gh < (unsigned)Hn) && ((unsigned)gw < (unsigned)Wn);
        const bool interior = active && (sq >= 1) && (sq <= 4) && (sr >= 2) && (sr < 18);
        const int xq_base = ((sr - 2) * 4 + (sq - 1));   // quad slot within channel

        const int c0 = quarter * CQ;
        const float4* src = (const float4*)(x)
                          + (valid ? ((img + gh * Wn + gw) >> 2) + c0 * (HWn >> 2) : 0);

        float4 a = make_float4(0.f, 0.f, 0.f, 0.f);
#pragma unroll 4
        for (int c = 0; c < CQ; c++) {
            float4 v = valid ? src[c * (HWn >> 2)]
                             : make_float4(0.f, 0.f, 0.f, 0.f);
            a.x = fmaf(v.x, v.x, a.x);
            a.y = fmaf(v.y, v.y, a.y);
            a.z = fmaf(v.z, v.z, a.z);
            a.w = fmaf(v.w, v.w, a.w);
            if (interior) x4_s[((c0 + c) << 6) + xq_base] = v;
        }
        if (active) part[quarter * NQ + p] = a;
    }
    __syncthreads();

    // reduce 4 partials -> s_s (scalar 20x24 grid)
    if (tid < NQ) {
        float4 a0 = part[tid];
        float4 a1 = part[NQ + tid];
        float4 a2 = part[2 * NQ + tid];
        float4 a3 = part[3 * NQ + tid];
        float4 s = make_float4(a0.x + a1.x + a2.x + a3.x,
                               a0.y + a1.y + a2.y + a3.y,
                               a0.z + a1.z + a2.z + a3.z,
                               a0.w + a1.w + a2.w + a3.w);
        const int sr = tid / SQ;
        const int sq = tid - sr * SQ;
        ((float4*)(s_s + sr * SCOLS))[sq] = s;     // row stride 96B: aligned
    }
    __syncthreads();

    // ---------------- Phase 2: 5x5 box filter + pow(-0.75) -------------------
    if (tid < NPIX) {
        const int i = tid >> 4;
        const int j = tid & 15;
        float sum = 0.0f;
#pragma unroll
        for (int di = 0; di < 5; di++) {
#pragma unroll
            for (int dj = 0; dj < 5; dj++) {
                sum += s_s[(i + di) * SCOLS + (j + 2 + dj)];
            }
        }
        const float bse = fmaf(1e-4f, sum, 2.0f);  // >= 2, safe for fast log
        f_s[tid] = __powf(bse, -0.75f);
    }
    __syncthreads();

    // ---------------- Phase 3: out = x * f from SMEM, float4 stores ----------
    const float4* f4 = (const float4*)f_s;         // [64] pixel quads
    float4* o4 = (float4*)out;
    const int obase = (img >> 2) + h0 * (Wn >> 2) + (w0 >> 2);
    const int stride4 = HWn >> 2;                  // 12544

#pragma unroll
    for (int k = 0; k < (Cn * NPIX / 4) / NTHREADS; k++) {   // 12 iterations
        const int idx = tid + k * NTHREADS;
        const int c  = idx >> 6;                   // 64 quads per channel
        const int q  = idx & 63;
        const int r  = q >> 2;                     // row in tile
        const int qw = q & 3;                      // quad within 16-wide row
        float4 v = x4_s[idx];
        const float4 f = f4[q];
        v.x *= f.x; v.y *= f.y; v.z *= f.z; v.w *= f.w;
        o4[obase + c * stride4 + r * (Wn >> 2) + qw] = v;
    }
}

extern "C" void kernel_launch(void* const* d_in, const int* in_sizes, int n_in,
                              void* d_out, int out_size) {
    const float* x = (const float*)d_in[0];
    float* out = (float*)d_out;
    cudaFuncSetAttribute(lrn_fused_kernel,
                         cudaFuncAttributeMaxDynamicSharedMemorySize, SMEM_BYTES);
    dim3 grid(Wn / TW, Hn / TH, Bn);   // 14 x 14 x 16 = 3136 blocks
    lrn_fused_kernel<<<grid, NTHREADS, SMEM_BYTES>>>(x, out);
}

// round 6
// speedup vs baseline: 1.4432x; 1.4432x over previous
#include <cuda_runtime.h>

// LRN, all-ones cross-channel 5x5 filter, 2-kernel split:
//   Kernel A: f[b,h,w] = (2 + 1e-4 * box5x5(sum_c x^2))^(-0.75)   (3.2 MB map)
//   Kernel B: out[b,c,h,w] = x[b,c,h,w] * f[b,h,w]                (pure stream)

#define Bn 16
#define Cn 96
#define Hn 224
#define Wn 224
#define HWn (Hn * Wn)          // 50176
#define HWq (HWn / 4)          // 12544 quads per channel-plane

// ---- Kernel A tiling ----
#define TILE 32
#define SROWS (TILE + 4)       // 36 halo rows
#define SQ 10                  // quads per halo row: [w0-4, w0+36) = 40 floats
#define SCOLS (SQ * 4)         // 40
#define NQ (SROWS * SQ)        // 360 halo quad positions
#define ATHREADS 384

__device__ float g_fmap[Bn * HWn];   // scale-factor map scratch (3.2 MB)

// ---------------------------------------------------------------------------
// Kernel A: channel-sum of squares (single read of x), 5x5 box, pow, -> g_fmap
// ---------------------------------------------------------------------------
__global__ __launch_bounds__(ATHREADS)
void lrn_fmap_kernel(const float* __restrict__ x) {
    __shared__ float s_s[SROWS * SCOLS];     // 36x40 summed squares (5.76 KB)

    const int tid = threadIdx.x;
    const int b   = blockIdx.z;
    const int h0  = blockIdx.y * TILE;
    const int w0  = blockIdx.x * TILE;

    // ---- Phase 1: each of 360 threads streams one halo quad over 96 channels
    if (tid < NQ) {
        const int sr = tid / SQ;
        const int sq = tid - sr * SQ;
        const int gh = h0 - 2 + sr;
        const int gw = w0 - 4 + sq * 4;      // quad fully in or fully out
        const bool valid = ((unsigned)gh < (unsigned)Hn) &&
                           ((unsigned)gw < (unsigned)Wn);

        float4 a = make_float4(0.f, 0.f, 0.f, 0.f);
        if (valid) {
            const float4* __restrict__ src = (const float4*)x
                + (size_t)b * Cn * HWq + ((gh * Wn + gw) >> 2);
#pragma unroll
            for (int c0 = 0; c0 < Cn; c0 += 8) {
                float4 v[8];
#pragma unroll
                for (int k = 0; k < 8; k++)
                    v[k] = __ldg(src + (c0 + k) * HWq);
#pragma unroll
                for (int k = 0; k < 8; k++) {
                    a.x = fmaf(v[k].x, v[k].x, a.x);
                    a.y = fmaf(v[k].y, v[k].y, a.y);
                    a.z = fmaf(v[k].z, v[k].z, a.z);
                    a.w = fmaf(v[k].w, v[k].w, a.w);
                }
            }
        }
        ((float4*)s_s)[tid] = a;
    }
    __syncthreads();

    // ---- Phase 2: 25-tap box filter + fast pow; write f map
#pragma unroll
    for (int p = tid; p < TILE * TILE; p += ATHREADS) {
        const int i = p >> 5;
        const int j = p & 31;
        float sum = 0.0f;
#pragma unroll
        for (int di = 0; di < 5; di++) {
#pragma unroll
            for (int dj = 0; dj < 5; dj++) {
                sum += s_s[(i + di) * SCOLS + (j + 2 + dj)];
            }
        }
        const float bse = fmaf(1e-4f, sum, 2.0f);    // >= 2, fast-log safe
        g_fmap[b * HWn + (h0 + i) * Wn + (w0 + j)] = __powf(bse, -0.75f);
    }
}

// ---------------------------------------------------------------------------
// Kernel B: out = x * f  (one thread per (b, pixel-quad), 96 channels each)
// ---------------------------------------------------------------------------
#define BTHREADS 256

__global__ __launch_bounds__(BTHREADS)
void lrn_scale_kernel(const float* __restrict__ x, float* __restrict__ out) {
    const int t = blockIdx.x * BTHREADS + threadIdx.x;   // 0 .. 16*12544-1
    const int b = t / HWq;
    const int q = t - b * HWq;

    const float4 f = __ldg((const float4*)g_fmap + t);   // t == b*HWq + q
    const float4* __restrict__ xp = (const float4*)x + (size_t)b * Cn * HWq + q;
    float4* __restrict__ op = (float4*)out + (size_t)b * Cn * HWq + q;

#pragma unroll
    for (int c0 = 0; c0 < Cn; c0 += 8) {
        float4 v[8];
#pragma unroll
        for (int k = 0; k < 8; k++)
            v[k] = __ldg(xp + (c0 + k) * HWq);
#pragma unroll
        for (int k = 0; k < 8; k++) {
            v[k].x *= f.x; v[k].y *= f.y; v[k].z *= f.z; v[k].w *= f.w;
            op[(c0 + k) * HWq] = v[k];
        }
    }
}

extern "C" void kernel_launch(void* const* d_in, const int* in_sizes, int n_in,
                              void* d_out, int out_size) {
    const float* x = (const float*)d_in[0];
    float* out = (float*)d_out;

    dim3 gridA(Wn / TILE, Hn / TILE, Bn);        // 7 x 7 x 16 = 784 blocks
    lrn_fmap_kernel<<<gridA, ATHREADS>>>(x);

    const int nquads = Bn * HWq;                 // 200704 threads
    lrn_scale_kernel<<<nquads / BTHREADS, BTHREADS>>>(x, out);
}

// round 7
// speedup vs baseline: 1.4617x; 1.0128x over previous
#include <cuda_runtime.h>

// LRN, all-ones cross-channel 5x5 filter, 3-kernel split:
//   A : s[b,h,w] = sum_c x^2                      (pure columnar reduction)
//   A2: f = (2 + 1e-4 * box5x5(s))^(-0.75)        (tiny, L2-resident)
//   B : out[b,c,h,w] = x[b,c,h,w] * f[b,h,w]      (pure stream)

#define Bn 16
#define Cn 96
#define Hn 224
#define Wn 224
#define HWn (Hn * Wn)          // 50176
#define HWq (HWn / 4)          // 12544 quads per channel-plane

__device__ float g_smap[Bn * HWn];   // channel-summed squares (3.2 MB)
__device__ float g_fmap[Bn * HWn];   // scale-factor map       (3.2 MB)

// ---------------------------------------------------------------------------
// Kernel A: s = sum_c x^2. One thread per (b, pixel-quad). No redundancy.
// ---------------------------------------------------------------------------
#define ATHREADS 256

__global__ __launch_bounds__(ATHREADS)
void lrn_ssq_kernel(const float* __restrict__ x) {
    const int t = blockIdx.x * ATHREADS + threadIdx.x;   // 0 .. 200703
    const int b = t / HWq;
    const int q = t - b * HWq;

    const float4* __restrict__ xp = (const float4*)x + (size_t)b * Cn * HWq + q;

    float4 a = make_float4(0.f, 0.f, 0.f, 0.f);
#pragma unroll
    for (int c0 = 0; c0 < Cn; c0 += 8) {
        float4 v[8];
#pragma unroll
        for (int k = 0; k < 8; k++)
            v[k] = __ldg(xp + (c0 + k) * HWq);
#pragma unroll
        for (int k = 0; k < 8; k++) {
            a.x = fmaf(v[k].x, v[k].x, a.x);
            a.y = fmaf(v[k].y, v[k].y, a.y);
            a.z = fmaf(v[k].z, v[k].z, a.z);
            a.w = fmaf(v[k].w, v[k].w, a.w);
        }
    }
    ((float4*)g_smap)[t] = a;
}

// ---------------------------------------------------------------------------
// Kernel A2: f = (2 + 1e-4 * box5x5(s))^(-0.75). Tiled, s is L2-resident.
// ---------------------------------------------------------------------------
#define TILE 32
#define SROWS (TILE + 4)       // 36
#define SQ 10                  // quads per halo row: [w0-4, w0+36)
#define SCOLS (SQ * 4)         // 40
#define NQ (SROWS * SQ)        // 360
#define A2THREADS 384

__global__ __launch_bounds__(A2THREADS)
void lrn_fmap_kernel() {
    __shared__ float s_s[SROWS * SCOLS];   // 5.76 KB

    const int tid = threadIdx.x;
    const int b   = blockIdx.z;
    const int h0  = blockIdx.y * TILE;
    const int w0  = blockIdx.x * TILE;

    if (tid < NQ) {
        const int sr = tid / SQ;
        const int sq = tid - sr * SQ;
        const int gh = h0 - 2 + sr;
        const int gw = w0 - 4 + sq * 4;    // quad fully in or out of image
        float4 v = make_float4(0.f, 0.f, 0.f, 0.f);
        if (((unsigned)gh < (unsigned)Hn) && ((unsigned)gw < (unsigned)Wn))
            v = __ldg((const float4*)g_smap + ((b * HWn + gh * Wn + gw) >> 2));
        ((float4*)s_s)[tid] = v;
    }
    __syncthreads();

#pragma unroll
    for (int p = tid; p < TILE * TILE; p += A2THREADS) {
        const int i = p >> 5;
        const int j = p & 31;
        float sum = 0.0f;
#pragma unroll
        for (int di = 0; di < 5; di++) {
#pragma unroll
            for (int dj = 0; dj < 5; dj++) {
                sum += s_s[(i + di) * SCOLS + (j + 2 + dj)];
            }
        }
        const float bse = fmaf(1e-4f, sum, 2.0f);   // >= 2, fast-log safe
        g_fmap[b * HWn + (h0 + i) * Wn + (w0 + j)] = __powf(bse, -0.75f);
    }
}

// ---------------------------------------------------------------------------
// Kernel B: out = x * f. One thread per (b, pixel-quad), 96 channels each.
// ---------------------------------------------------------------------------
#define BTHREADS 256

__global__ __launch_bounds__(BTHREADS)
void lrn_scale_kernel(const float* __restrict__ x, float* __restrict__ out) {
    const int t = blockIdx.x * BTHREADS + threadIdx.x;
    const int b = t / HWq;
    const int q = t - b * HWq;

    const float4 f = __ldg((const float4*)g_fmap + t);
    const float4* __restrict__ xp = (const float4*)x + (size_t)b * Cn * HWq + q;
    float4* __restrict__ op = (float4*)out + (size_t)b * Cn * HWq + q;

#pragma unroll
    for (int c0 = 0; c0 < Cn; c0 += 8) {
        float4 v[8];
#pragma unroll
        for (int k = 0; k < 8; k++)
            v[k] = __ldg(xp + (c0 + k) * HWq);
#pragma unroll
        for (int k = 0; k < 8; k++) {
            v[k].x *= f.x; v[k].y *= f.y; v[k].z *= f.z; v[k].w *= f.w;
            op[(c0 + k) * HWq] = v[k];
        }
    }
}

extern "C" void kernel_launch(void* const* d_in, const int* in_sizes, int n_in,
                              void* d_out, int out_size) {
    const float* x = (const float*)d_in[0];
    float* out = (float*)d_out;

    const int nquads = Bn * HWq;                  // 200704
    lrn_ssq_kernel<<<nquads / ATHREADS, ATHREADS>>>(x);

    dim3 gridA2(Wn / TILE, Hn / TILE, Bn);        // 7 x 7 x 16
    lrn_fmap_kernel<<<gridA2, A2THREADS>>>();

    lrn_scale_kernel<<<nquads / BTHREADS, BTHREADS>>>(x, out);
}

// round 8
// speedup vs baseline: 1.4854x; 1.0162x over previous
#include <cuda_runtime.h>

// LRN, all-ones cross-channel 5x5 filter, 2-kernel split:
//   A: s[b,h,w] = sum_c x^2                       (pure columnar reduction)
//   B: f = (2 + 1e-4 * box5x5(s))^(-0.75) computed inline from L2-resident s;
//      out[b,c,h,w] = x[b,c,h,w] * f              (pure stream)

#define Bn 16
#define Cn 96
#define Hn 224
#define Wn 224
#define HWn (Hn * Wn)          // 50176
#define HWq (HWn / 4)          // 12544 quads per channel-plane
#define WQ (Wn / 4)            // 56 quads per row

__device__ float g_smap[Bn * HWn];   // channel-summed squares (3.2 MB)

// ---------------------------------------------------------------------------
// Kernel A: s = sum_c x^2. One thread per (b, pixel-quad). No redundancy.
// ---------------------------------------------------------------------------
#define ATHREADS 256

__global__ __launch_bounds__(ATHREADS)
void lrn_ssq_kernel(const float* __restrict__ x) {
    const int t = blockIdx.x * ATHREADS + threadIdx.x;   // 0 .. 200703
    const int b = t / HWq;
    const int q = t - b * HWq;

    const float4* __restrict__ xp = (const float4*)x + (size_t)b * Cn * HWq + q;

    float4 a = make_float4(0.f, 0.f, 0.f, 0.f);
#pragma unroll
    for (int c0 = 0; c0 < Cn; c0 += 8) {
        float4 v[8];
#pragma unroll
        for (int k = 0; k < 8; k++)
            v[k] = __ldg(xp + (c0 + k) * HWq);
#pragma unroll
        for (int k = 0; k < 8; k++) {
            a.x = fmaf(v[k].x, v[k].x, a.x);
            a.y = fmaf(v[k].y, v[k].y, a.y);
            a.z = fmaf(v[k].z, v[k].z, a.z);
            a.w = fmaf(v[k].w, v[k].w, a.w);
        }
    }
    ((float4*)g_smap)[t] = a;
}

// ---------------------------------------------------------------------------
// Kernel B: inline box5x5(s) + pow, then out = x * f. One thread per
// (b, pixel-quad); s-window loads hit L2 (s map is 3.2 MB, just written by A).
// ---------------------------------------------------------------------------
#define BTHREADS 256

__global__ __launch_bounds__(BTHREADS)
void lrn_scale_kernel(const float* __restrict__ x, float* __restrict__ out) {
    const int t = blockIdx.x * BTHREADS + threadIdx.x;
    const int b = t / HWq;
    const int q = t - b * HWq;
    const int r  = q / WQ;          // pixel row 0..223
    const int jq = q - r * WQ;      // quad column 0..55

    // ---- vertical sum of s over rows r-2..r+2, 12 columns [4*jq-4, 4*jq+8)
    float vs[12];
#pragma unroll
    for (int k = 0; k < 12; k++) vs[k] = 0.0f;

    const float4* __restrict__ s4 = (const float4*)g_smap;
#pragma unroll
    for (int dh = -2; dh <= 2; dh++) {
        const int h2 = r + dh;
        if ((unsigned)h2 < (unsigned)Hn) {
            const int rowq = (b * HWn + h2 * Wn) >> 2;
#pragma unroll
            for (int tq = 0; tq < 3; tq++) {
                const int qi = jq - 1 + tq;
                if ((unsigned)qi < (unsigned)WQ) {
                    const float4 v = __ldg(s4 + rowq + qi);
                    vs[tq * 4 + 0] += v.x;
                    vs[tq * 4 + 1] += v.y;
                    vs[tq * 4 + 2] += v.z;
                    vs[tq * 4 + 3] += v.w;
                }
            }
        }
    }

    // ---- horizontal 5-tap sums + fast pow: pixel p needs vs[2+p .. 6+p]
    float4 f;
    {
        float y0 = vs[2] + vs[3] + vs[4] + vs[5] + vs[6];
        float y1 = vs[3] + vs[4] + vs[5] + vs[6] + vs[7];
        float y2 = vs[4] + vs[5] + vs[6] + vs[7] + vs[8];
        float y3 = vs[5] + vs[6] + vs[7] + vs[8] + vs[9];
        f.x = __powf(fmaf(1e-4f, y0, 2.0f), -0.75f);   // base >= 2: fast-log safe
        f.y = __powf(fmaf(1e-4f, y1, 2.0f), -0.75f);
        f.z = __powf(fmaf(1e-4f, y2, 2.0f), -0.75f);
        f.w = __powf(fmaf(1e-4f, y3, 2.0f), -0.75f);
    }

    // ---- main stream: out = x * f over 96 channels
    const float4* __restrict__ xp = (const float4*)x + (size_t)b * Cn * HWq + q;
    float4* __restrict__ op = (float4*)out + (size_t)b * Cn * HWq + q;

#pragma unroll
    for (int c0 = 0; c0 < Cn; c0 += 8) {
        float4 v[8];
#pragma unroll
        for (int k = 0; k < 8; k++)
            v[k] = __ldg(xp + (c0 + k) * HWq);
#pragma unroll
        for (int k = 0; k < 8; k++) {
            v[k].x *= f.x; v[k].y *= f.y; v[k].z *= f.z; v[k].w *= f.w;
            op[(c0 + k) * HWq] = v[k];
        }
    }
}

extern "C" void kernel_launch(void* const* d_in, const int* in_sizes, int n_in,
                              void* d_out, int out_size) {
    const float* x = (const float*)d_in[0];
    float* out = (float*)d_out;

    const int nquads = Bn * HWq;                  // 200704
    lrn_ssq_kernel<<<nquads / ATHREADS, ATHREADS>>>(x);
    lrn_scale_kernel<<<nquads / BTHREADS, BTHREADS>>>(x, out);
}

// round 12
// speedup vs baseline: 1.6223x; 1.0922x over previous
#include <cuda_runtime.h>

// LRN, all-ones cross-channel 5x5 filter, 2-kernel split:
//   A: s[b,h,w] = sum_c x^2                       (pure columnar reduction)
//   B: f = (2 + 1e-4 * box5x5(s))^(-0.75) inline from L2-resident s;
//      out = x * f, channels iterated in REVERSE so the first re-reads of x
//      hit the L2 tail that kernel A (single wave, lockstep channel sweep)
//      just left behind. Streaming hints (__ldcs/__stcs) keep that tail hot.

#define Bn 16
#define Cn 96
#define Hn 224
#define Wn 224
#define HWn (Hn * Wn)          // 50176
#define HWq (HWn / 4)          // 12544 quads per channel-plane
#define WQ (Wn / 4)            // 56 quads per row

__device__ float g_smap[Bn * HWn];   // channel-summed squares (3.2 MB)

// ---------------------------------------------------------------------------
// Kernel A: s = sum_c x^2. One thread per (b, pixel-quad). No redundancy.
// ---------------------------------------------------------------------------
#define ATHREADS 256

__global__ __launch_bounds__(ATHREADS)
void lrn_ssq_kernel(const float* __restrict__ x) {
    const int t = blockIdx.x * ATHREADS + threadIdx.x;   // 0 .. 200703
    const int b = t / HWq;
    const int q = t - b * HWq;

    const float4* __restrict__ xp = (const float4*)x + (size_t)b * Cn * HWq + q;

    float4 a = make_float4(0.f, 0.f, 0.f, 0.f);
#pragma unroll
    for (int c0 = 0; c0 < Cn; c0 += 8) {
        float4 v[8];
#pragma unroll
        for (int k = 0; k < 8; k++)
            v[k] = __ldg(xp + (c0 + k) * HWq);
#pragma unroll
        for (int k = 0; k < 8; k++) {
            a.x = fmaf(v[k].x, v[k].x, a.x);
            a.y = fmaf(v[k].y, v[k].y, a.y);
            a.z = fmaf(v[k].z, v[k].z, a.z);
            a.w = fmaf(v[k].w, v[k].w, a.w);
        }
    }
    ((float4*)g_smap)[t] = a;
}

// ---------------------------------------------------------------------------
// Kernel B: inline box5x5(s) + pow, then out = x * f (reverse channel sweep).
// ---------------------------------------------------------------------------
#define BTHREADS 256

__global__ __launch_bounds__(BTHREADS)
void lrn_scale_kernel(const float* __restrict__ x, float* __restrict__ out) {
    const int t = blockIdx.x * BTHREADS + threadIdx.x;
    const int b = t / HWq;
    const int q = t - b * HWq;
    const int r  = q / WQ;          // pixel row 0..223
    const int jq = q - r * WQ;      // quad column 0..55

    // ---- vertical sum of s over rows r-2..r+2, 12 columns [4*jq-4, 4*jq+8)
    float vs[12];
#pragma unroll
    for (int k = 0; k < 12; k++) vs[k] = 0.0f;

    const float4* __restrict__ s4 = (const float4*)g_smap;
#pragma unroll
    for (int dh = -2; dh <= 2; dh++) {
        const int h2 = r + dh;
        if ((unsigned)h2 < (unsigned)Hn) {
            const int rowq = (b * HWn + h2 * Wn) >> 2;
#pragma unroll
            for (int tq = 0; tq < 3; tq++) {
                const int qi = jq - 1 + tq;
                if ((unsigned)qi < (unsigned)WQ) {
                    const float4 v = __ldg(s4 + rowq + qi);
                    vs[tq * 4 + 0] += v.x;
                    vs[tq * 4 + 1] += v.y;
                    vs[tq * 4 + 2] += v.z;
                    vs[tq * 4 + 3] += v.w;
                }
            }
        }
    }

    // ---- horizontal 5-tap sums + fast pow: pixel p needs vs[2+p .. 6+p]
    float4 f;
    {
        float y0 = vs[2] + vs[3] + vs[4] + vs[5] + vs[6];
        float y1 = vs[3] + vs[4] + vs[5] + vs[6] + vs[7];
        float y2 = vs[4] + vs[5] + vs[6] + vs[7] + vs[8];
        float y3 = vs[5] + vs[6] + vs[7] + vs[8] + vs[9];
        f.x = __powf(fmaf(1e-4f, y0, 2.0f), -0.75f);   // base >= 2: fast-log safe
        f.y = __powf(fmaf(1e-4f, y1, 2.0f), -0.75f);
        f.z = __powf(fmaf(1e-4f, y2, 2.0f), -0.75f);
        f.w = __powf(fmaf(1e-4f, y3, 2.0f), -0.75f);
    }

    // ---- main stream: out = x * f, channels in REVERSE (hit A's L2 tail).
    const float4* __restrict__ xp = (const float4*)x + (size_t)b * Cn * HWq + q;
    float4* __restrict__ op = (float4*)out + (size_t)b * Cn * HWq + q;

#pragma unroll
    for (int c0 = Cn - 8; c0 >= 0; c0 -= 8) {
        float4 v[8];
#pragma unroll
        for (int k = 7; k >= 0; k--)
            v[k] = __ldcs(xp + (c0 + k) * HWq);      // dead after use: evict-first
#pragma unroll
        for (int k = 7; k >= 0; k--) {
            v[k].x *= f.x; v[k].y *= f.y; v[k].z *= f.z; v[k].w *= f.w;
            __stcs(op + (c0 + k) * HWq, v[k]);       // never re-read: streaming
        }
    }
}

extern "C" void kernel_launch(void* const* d_in, const int* in_sizes, int n_in,
                              void* d_out, int out_size) {
    const float* x = (const float*)d_in[0];
    float* out = (float*)d_out;

    const int nquads = Bn * HWq;                  // 200704
    lrn_ssq_kernel<<<nquads / ATHREADS, ATHREADS>>>(x);
    lrn_scale_kernel<<<nquads / BTHREADS, BTHREADS>>>(x, out);
}

// round 13
// speedup vs baseline: 1.6328x; 1.0065x over previous
#include <cuda_runtime.h>

// LRN, all-ones cross-channel 5x5 filter, 2-kernel split + PDL overlap:
//   A: s[b,h,w] = sum_c x^2        (pure columnar reduction, triggers B early)
//   B: f = (2 + 1e-4 * box5x5(s))^(-0.75) inline from L2-resident s;
//      out = x * f, reverse channel sweep (hits A's L2 tail), streaming hints.
//      B prefetches its first x batch BEFORE cudaGridDependencySynchronize().

#define Bn 16
#define Cn 96
#define Hn 224
#define Wn 224
#define HWn (Hn * Wn)          // 50176
#define HWq (HWn / 4)          // 12544 quads per channel-plane
#define WQ (Wn / 4)            // 56 quads per row

__device__ float g_smap[Bn * HWn];   // channel-summed squares (3.2 MB)

// ---------------------------------------------------------------------------
// Kernel A: s = sum_c x^2. One thread per (b, pixel-quad). No redundancy.
// ---------------------------------------------------------------------------
#define ATHREADS 256

__global__ __launch_bounds__(ATHREADS)
void lrn_ssq_kernel(const float* __restrict__ x) {
    const int t = blockIdx.x * ATHREADS + threadIdx.x;   // 0 .. 200703
    const int b = t / HWq;
    const int q = t - b * HWq;

    const float4* __restrict__ xp = (const float4*)x + (size_t)b * Cn * HWq + q;

    float4 a = make_float4(0.f, 0.f, 0.f, 0.f);
#pragma unroll
    for (int c0 = 0; c0 < Cn; c0 += 8) {
        float4 v[8];
#pragma unroll
        for (int k = 0; k < 8; k++)
            v[k] = __ldg(xp + (c0 + k) * HWq);
#pragma unroll
        for (int k = 0; k < 8; k++) {
            a.x = fmaf(v[k].x, v[k].x, a.x);
            a.y = fmaf(v[k].y, v[k].y, a.y);
            a.z = fmaf(v[k].z, v[k].z, a.z);
            a.w = fmaf(v[k].w, v[k].w, a.w);
        }
    }
    ((float4*)g_smap)[t] = a;

    // Let the dependent kernel B launch as soon as all blocks reach here.
    cudaTriggerProgrammaticLaunchCompletion();
}

// ---------------------------------------------------------------------------
// Kernel B: prefetch first x batch (A-independent), grid-dependency sync,
// inline box5x5(s) + pow, then out = x * f (reverse channel sweep).
// ---------------------------------------------------------------------------
#define BTHREADS 256

__global__ __launch_bounds__(BTHREADS)
void lrn_scale_kernel(const float* __restrict__ x, float* __restrict__ out) {
    const int t = blockIdx.x * BTHREADS + threadIdx.x;
    const int b = t / HWq;
    const int q = t - b * HWq;
    const int r  = q / WQ;          // pixel row 0..223
    const int jq = q - r * WQ;      // quad column 0..55

    const float4* __restrict__ xp = (const float4*)x + (size_t)b * Cn * HWq + q;
    float4* __restrict__ op = (float4*)out + (size_t)b * Cn * HWq + q;

    // ---- A-independent prefetch: first reverse batch (channels 88..95)
    float4 pv[8];
    {
        const int c0 = Cn - 8;
#pragma unroll
        for (int k = 0; k < 8; k++)
            pv[k] = __ldcs(xp + (c0 + k) * HWq);
    }

    // ---- wait for kernel A's g_smap writes to be visible
    cudaGridDependencySynchronize();

    // ---- vertical sum of s over rows r-2..r+2, 12 columns [4*jq-4, 4*jq+8)
    float vs[12];
#pragma unroll
    for (int k = 0; k < 12; k++) vs[k] = 0.0f;

    const float4* __restrict__ s4 = (const float4*)g_smap;
#pragma unroll
    for (int dh = -2; dh <= 2; dh++) {
        const int h2 = r + dh;
        if ((unsigned)h2 < (unsigned)Hn) {
            const int rowq = (b * HWn + h2 * Wn) >> 2;
#pragma unroll
            for (int tq = 0; tq < 3; tq++) {
                const int qi = jq - 1 + tq;
                if ((unsigned)qi < (unsigned)WQ) {
                    const float4 v = __ldg(s4 + rowq + qi);
                    vs[tq * 4 + 0] += v.x;
                    vs[tq * 4 + 1] += v.y;
                    vs[tq * 4 + 2] += v.z;
                    vs[tq * 4 + 3] += v.w;
                }
            }
        }
    }

    // ---- horizontal 5-tap sums + fast pow: pixel p needs vs[2+p .. 6+p]
    float4 f;
    {
        float y0 = vs[2] + vs[3] + vs[4] + vs[5] + vs[6];
        float y1 = vs[3] + vs[4] + vs[5] + vs[6] + vs[7];
        float y2 = vs[4] + vs[5] + vs[6] + vs[7] + vs[8];
        float y3 = vs[5] + vs[6] + vs[7] + vs[8] + vs[9];
        f.x = __powf(fmaf(1e-4f, y0, 2.0f), -0.75f);   // base >= 2: fast-log safe
        f.y = __powf(fmaf(1e-4f, y1, 2.0f), -0.75f);
        f.z = __powf(fmaf(1e-4f, y2, 2.0f), -0.75f);
        f.w = __powf(fmaf(1e-4f, y3, 2.0f), -0.75f);
    }

    // ---- consume prefetched batch (channels 88..95)
    {
        const int c0 = Cn - 8;
#pragma unroll
        for (int k = 7; k >= 0; k--) {
            pv[k].x *= f.x; pv[k].y *= f.y; pv[k].z *= f.z; pv[k].w *= f.w;
            __stcs(op + (c0 + k) * HWq, pv[k]);
        }
    }

    // ---- remaining channels in REVERSE (hit A's L2 tail first)
#pragma unroll
    for (int c0 = Cn - 16; c0 >= 0; c0 -= 8) {
        float4 v[8];
#pragma unroll
        for (int k = 7; k >= 0; k--)
            v[k] = __ldcs(xp + (c0 + k) * HWq);      // dead after use
#pragma unroll
        for (int k = 7; k >= 0; k--) {
            v[k].x *= f.x; v[k].y *= f.y; v[k].z *= f.z; v[k].w *= f.w;
            __stcs(op + (c0 + k) * HWq, v[k]);       // never re-read
        }
    }
}

extern "C" void kernel_launch(void* const* d_in, const int* in_sizes, int n_in,
                              void* d_out, int out_size) {
    const float* x = (const float*)d_in[0];
    float* out = (float*)d_out;

    const int nquads = Bn * HWq;                  // 200704
    lrn_ssq_kernel<<<nquads / ATHREADS, ATHREADS>>>(x);

    // Kernel B: programmatic dependent launch (overlaps with A's tail).
    cudaLaunchAttribute attrs[1];
    attrs[0].id = cudaLaunchAttributeProgrammaticStreamSerialization;
    attrs[0].val.programmaticStreamSerializationAllowed = 1;

    cudaLaunchConfig_t cfg = {};
    cfg.gridDim  = dim3(nquads / BTHREADS, 1, 1);
    cfg.blockDim = dim3(BTHREADS, 1, 1);
    cfg.dynamicSmemBytes = 0;
    cfg.stream = 0;
    cfg.attrs = attrs;
    cfg.numAttrs = 1;
    cudaLaunchKernelEx(&cfg, lrn_scale_kernel, x, out);
}